// round 9
// baseline (speedup 1.0000x reference)
#include <cuda_runtime.h>
#include <cuda_fp16.h>
#include <cstdint>

typedef unsigned long long u64;
typedef unsigned int u32;

constexpr int K_N  = 65536;
constexpr int K_IC = 1024;
constexpr int K_E  = 300;
constexpr int K_C  = 81;
constexpr int K_C4 = 324;
constexpr int K_NC = K_E + K_C4;   // 624
constexpr int K_NPAD = 640;        // padded W rows
constexpr int PVLD = 320;          // padded pv row length (halves)

// ---------------- scratch ----------------
__device__ __half g_wh[(size_t)K_NPAD * K_IC];   // [Wf;Wb] fp16, rows>=624 zero
__device__ __half g_pvh[(size_t)K_N * PVLD];     // projected_visual fp16, cols>=300 zero
__device__ __half g_neh[96 * PVLD];              // l2norm(proj_emb) fp16, padded zero
__device__ float g_pe[K_C * K_E];                // projected_emb fp32 (triplet)
__device__ float g_sen[K_C * K_E];
__device__ float g_S[K_C * K_C];

// ---------------- helpers ----------------
__device__ __forceinline__ u32 smem_u32(const void* p) {
    u32 a;
    asm("{ .reg .u64 t; cvta.to.shared.u64 t, %1; cvt.u32.u64 %0, t; }" : "=r"(a) : "l"(p));
    return a;
}
__device__ __forceinline__ u32 sw128(u32 off) { return off ^ ((off >> 3) & 0x70); }

#define CP_ASYNC16(dst, src) \
    asm volatile("cp.async.cg.shared.global [%0], [%1], 16;" :: "r"(dst), "l"(src) : "memory")
#define CP_COMMIT() asm volatile("cp.async.commit_group;" ::: "memory")
#define CP_WAIT1()  asm volatile("cp.async.wait_group 1;" ::: "memory")
#define CP_WAIT0()  asm volatile("cp.async.wait_group 0;" ::: "memory")

__device__ __forceinline__ void ldsm_x4(u32 addr, u32& r0, u32& r1, u32& r2, u32& r3) {
    asm volatile("ldmatrix.sync.aligned.m8n8.x4.shared.b16 {%0,%1,%2,%3}, [%4];"
                 : "=r"(r0), "=r"(r1), "=r"(r2), "=r"(r3) : "r"(addr));
}
__device__ __forceinline__ void mma_f16(float* d, const u32* a, u32 b0, u32 b1) {
    asm volatile(
        "mma.sync.aligned.m16n8k16.row.col.f32.f16.f16.f32 "
        "{%0,%1,%2,%3}, {%4,%5,%6,%7}, {%8,%9}, {%0,%1,%2,%3};"
        : "+f"(d[0]), "+f"(d[1]), "+f"(d[2]), "+f"(d[3])
        : "r"(a[0]), "r"(a[1]), "r"(a[2]), "r"(a[3]), "r"(b0), "r"(b1));
}
__device__ __forceinline__ u32 h2u(__half2 h) { return *reinterpret_cast<u32*>(&h); }

// ---------------- prep: W rows -> fp16, pad to 640 rows ----------------
__global__ void whalf_kernel(const float* __restrict__ Wf, const float* __restrict__ Wb)
{
    const int row = blockIdx.x;          // 0..639
    const int c4  = threadIdx.x;         // 0..255
    float4 v = make_float4(0.f, 0.f, 0.f, 0.f);
    if (row < K_E)        v = *(const float4*)(Wf + (size_t)row * K_IC + c4 * 4);
    else if (row < K_NC)  v = *(const float4*)(Wb + (size_t)(row - K_E) * K_IC + c4 * 4);
    __half2 h01 = __floats2half2_rn(v.x, v.y);
    __half2 h23 = __floats2half2_rn(v.z, v.w);
    uint2 hu = make_uint2(h2u(h01), h2u(h23));
    *(uint2*)(g_wh + (size_t)row * K_IC + c4 * 4) = hu;
}

// ---------------- pe: projected_emb + normalized fp16 table ----------------
__global__ void pe_kernel(const float* __restrict__ se,
                          const float* __restrict__ We,
                          const float* __restrict__ be)
{
    const int c = blockIdx.x;
    const int e = threadIdx.x;             // 0..319
    if (c >= K_C) {
        g_neh[c * PVLD + e] = __float2half(0.f);
        return;
    }
    __shared__ float srow[K_E];
    __shared__ float red[320];
    for (int k = e; k < K_E; k += 320) srow[k] = se[(size_t)c * K_E + k];
    __syncthreads();
    float v = 0.f;
    if (e < K_E) {
        const float* w = We + (size_t)e * K_E;
        float s = 0.f;
        for (int k = 0; k < K_E; k++) s = fmaf(srow[k], w[k], s);
        v = s + be[e];
        g_pe[(size_t)c * K_E + e] = v;
    }
    red[e] = v * v;
    __syncthreads();
    if (e == 0) {
        float s = 0.f;
        for (int i = 0; i < 320; i++) s += red[i];
        red[0] = 1.f / fmaxf(sqrtf(s), 1e-12f);
    }
    __syncthreads();
    g_neh[c * PVLD + e] = __float2half((e < K_E) ? v * red[0] : 0.f);
}

// ---------------- triplet stages ----------------
__global__ void norm_sen_kernel(const float* __restrict__ se)
{
    const int c = blockIdx.x;
    const int t = threadIdx.x;
    __shared__ float red[128];
    float s = 0.f;
    const float* row = se + (size_t)c * K_E;
    for (int k = t; k < K_E; k += 128) { float v = row[k]; s = fmaf(v, v, s); }
    red[t] = s;
    __syncthreads();
    #pragma unroll
    for (int off = 64; off > 0; off >>= 1) {
        if (t < off) red[t] += red[t + off];
        __syncthreads();
    }
    const float inv = 1.f / fmaxf(sqrtf(red[0]), 1e-12f);
    for (int k = t; k < K_E; k += 128) g_sen[(size_t)c * K_E + k] = row[k] * inv;
}

__global__ void sim_kernel()
{
    const int i = blockIdx.x;
    const int t = threadIdx.x;
    const int w = t >> 5, l = t & 31;
    __shared__ float rowi[K_E];
    for (int k = t; k < K_E; k += 256) rowi[k] = g_sen[(size_t)i * K_E + k];
    __syncthreads();
    for (int j = w; j < K_C; j += 8) {
        const float* b = g_sen + (size_t)j * K_E;
        float s = 0.f;
        for (int k = l; k < K_E; k += 32) s = fmaf(rowi[k], b[k], s);
        #pragma unroll
        for (int o = 16; o > 0; o >>= 1) s += __shfl_xor_sync(0xffffffffu, s, o);
        if (l == 0) g_S[i * K_C + j] = s;
    }
}

__global__ void loss_kernel(float* __restrict__ out_loss)
{
    const int t = threadIdx.x;             // 96
    __shared__ float red[96];
    float contrib = 0.f;
    if (t < K_C) {
        const float* Srow = g_S + (size_t)t * K_C;
        float mx = -1e30f;
        for (int j = 0; j < K_C; j++) {
            float v = Srow[j];
            if (v != 1.0f) mx = fmaxf(mx, v);
        }
        float sum = 0.f;
        for (int j = 0; j < K_C; j++) {
            float v = Srow[j];
            if (v != 1.0f) sum += expf(v - mx);
        }
        float m1 = -1e30f, m2 = -1e30f; int i1 = -1, i2 = -1;
        float mn = 1e30f; int imn = -1;
        for (int j = 0; j < K_C; j++) {
            float v = Srow[j];
            float sm = (v == 1.0f) ? v : (expf(v - mx) / sum);
            if (sm > m1)      { m2 = m1; i2 = i1; m1 = sm; i1 = j; }
            else if (sm > m2) { m2 = sm; i2 = j; }
            if (sm <= mn)     { mn = sm; imn = j; }
        }
        const int ms = i2, ls = imn;
        const float margin = m2 - mn;
        const float* pi = g_pe + (size_t)t  * K_E;
        const float* pm = g_pe + (size_t)ms * K_E;
        const float* pl = g_pe + (size_t)ls * K_E;
        float ds = 0.f, dd = 0.f;
        for (int k = 0; k < K_E; k++) {
            float d1 = pi[k] - pm[k]; ds = fmaf(d1, d1, ds);
            float d2 = pi[k] - pl[k]; dd = fmaf(d2, d2, dd);
        }
        contrib = fmaxf(0.f, sqrtf(ds) - sqrtf(dd) + margin);
    }
    red[t] = contrib;
    __syncthreads();
    if (t == 0) {
        float s = 0.f;
        for (int i = 0; i < 96; i++) s += red[i];
        out_loss[0] = s / (float)K_C;
    }
}

// ---------------- main GEMM: fused fp32->fp16 A path + cp.async B, 2 stages ----------------
constexpr int BM = 128, BN = 128, BK = 64;
constexpr int NKT = K_IC / BK;         // 16
constexpr int AB = BM * BK * 2;        // 16384 (A fp16)
constexpr int STGB = 2 * AB;           // 32768 per stage (A + B)
constexpr int GEMM_SMEM = 2 * STGB;    // 65536

// A: each thread owns 4 chunks (16B fp16 each) = 8 float4 of x
__device__ __forceinline__ void lda(float4* ar, const float* __restrict__ x,
                                    int row0, int tid, int kt)
{
    const int koff = kt * BK;
    #pragma unroll
    for (int i = 0; i < 4; i++) {
        const int q = i * 256 + tid;
        const int row = q >> 3, kb = q & 7;
        const float* src = x + (size_t)(row0 + row) * K_IC + koff + kb * 8;
        ar[i * 2]     = *(const float4*)src;
        ar[i * 2 + 1] = *(const float4*)(src + 4);
    }
}
__device__ __forceinline__ void sta(u32 sdst, const float4* ar, int tid)
{
    #pragma unroll
    for (int i = 0; i < 4; i++) {
        const int q = i * 256 + tid;
        const int row = q >> 3, kb = q & 7;
        const u32 v0 = h2u(__floats2half2_rn(ar[i*2].x,   ar[i*2].y));
        const u32 v1 = h2u(__floats2half2_rn(ar[i*2].z,   ar[i*2].w));
        const u32 v2 = h2u(__floats2half2_rn(ar[i*2+1].x, ar[i*2+1].y));
        const u32 v3 = h2u(__floats2half2_rn(ar[i*2+1].z, ar[i*2+1].w));
        asm volatile("st.shared.v4.b32 [%0], {%1,%2,%3,%4};"
                     :: "r"(sdst + sw128((u32)(row * 128 + kb * 16))),
                        "r"(v0), "r"(v1), "r"(v2), "r"(v3) : "memory");
    }
}
__device__ __forceinline__ void ldb(u32 sdst, int tid, int nc0, int kt)
{
    const int koff = kt * BK;
    #pragma unroll
    for (int i = 0; i < 4; i++) {
        const int q = i * 256 + tid;
        const int row = q >> 3, kb = q & 7;
        const __half* src = g_wh + (size_t)(nc0 + row) * K_IC + koff + kb * 8;
        CP_ASYNC16(sdst + AB + sw128((u32)(row * 128 + kb * 16)), src);
    }
}

__global__ __launch_bounds__(256, 2)
void gemm_kernel(const float* __restrict__ x,
                 const float* __restrict__ bfp, const float* __restrict__ bbp,
                 float* __restrict__ out_bbox)
{
    extern __shared__ char smem[];
    __shared__ float sbias[BN];
    const u32 sb = smem_u32(smem);

    const int tid  = threadIdx.x;
    const int wid  = tid >> 5;
    const int lane = tid & 31;
    const int wm   = wid & 3;
    const int wn   = wid >> 2;
    const int nc0  = blockIdx.x * BN;
    const int row0 = blockIdx.y * BM;

    if (tid < BN) {
        const int gc = nc0 + tid;
        sbias[tid] = (gc < K_E) ? bfp[gc] : ((gc < K_NC) ? bbp[gc - K_E] : 0.f);
    }

    float acc[2][8][4];
    #pragma unroll
    for (int mt = 0; mt < 2; mt++)
        #pragma unroll
        for (int nt = 0; nt < 8; nt++)
            #pragma unroll
            for (int i = 0; i < 4; i++) acc[mt][nt][i] = 0.f;

    float4 ar[8];
    // prologue
    lda(ar, x, row0, tid, 0);
    ldb(sb, tid, nc0, 0);          CP_COMMIT();   // g0 = B0
    sta(sb, ar, tid);                              // A0 -> stage0
    lda(ar, x, row0, tid, 1);                      // A1 in regs
    ldb(sb + STGB, tid, nc0, 1);   CP_COMMIT();   // g1 = B1
    CP_WAIT1();                                    // B0 done
    __syncthreads();                               // A0 visible

    const int lr15 = lane & 15;
    const int lkc  = lane >> 4;

    for (int kt = 0; kt < NKT; kt++) {
        const u32 abase = sb + (kt & 1) * STGB;
        const u32 bbase = abase + AB;
        #pragma unroll
        for (int j = 0; j < 4; j++) {
            const int kc = j * 2 + lkc;
            u32 a[2][4], b[4][4];
            #pragma unroll
            for (int mt = 0; mt < 2; mt++) {
                const int r = wm * 32 + mt * 16 + lr15;
                ldsm_x4(abase + sw128((u32)(r * 128 + kc * 16)),
                        a[mt][0], a[mt][1], a[mt][2], a[mt][3]);
            }
            #pragma unroll
            for (int nt4 = 0; nt4 < 4; nt4++) {
                const int r = wn * 64 + nt4 * 16 + lr15;
                ldsm_x4(bbase + sw128((u32)(r * 128 + kc * 16)),
                        b[nt4][0], b[nt4][1], b[nt4][2], b[nt4][3]);
            }
            #pragma unroll
            for (int mt = 0; mt < 2; mt++)
                #pragma unroll
                for (int nt4 = 0; nt4 < 4; nt4++) {
                    mma_f16(acc[mt][nt4 * 2 + 0], a[mt], b[nt4][0], b[nt4][2]);
                    mma_f16(acc[mt][nt4 * 2 + 1], a[mt], b[nt4][1], b[nt4][3]);
                }
        }
        if (kt + 1 < NKT) {
            __syncthreads();   // all warps done compute(kt): both stages' old data reusable
            sta(sb + ((kt + 1) & 1) * STGB, ar, tid);   // A(kt+1)
            if (kt + 2 < NKT) {
                lda(ar, x, row0, tid, kt + 2);          // A(kt+2) regs (latency hidden)
                ldb(sb + (kt & 1) * STGB, tid, nc0, kt + 2);  // B(kt+2) -> stage kt&1
            }
            CP_COMMIT();       // group for B(kt+2) (possibly empty)
            CP_WAIT1();        // only B(kt+2) outstanding => B(kt+1) done
            __syncthreads();   // A STS + B visible
        }
    }

    // ---- epilogue: bias + scatter (pv fp16, bbox fp32) ----
    const int lr = lane >> 2;
    const int lc = (lane & 3) * 2;
    #pragma unroll
    for (int mt = 0; mt < 2; mt++) {
        const int r0 = row0 + wm * 32 + mt * 16 + lr;
        #pragma unroll
        for (int nt = 0; nt < 8; nt++) {
            const int lcol = wn * 64 + nt * 8 + lc;
            const int gc = nc0 + lcol;
            if (gc >= K_NC) continue;
            const float b0 = sbias[lcol], b1 = sbias[lcol + 1];
            float2 v0 = make_float2(acc[mt][nt][0] + b0, acc[mt][nt][1] + b1);
            float2 v1 = make_float2(acc[mt][nt][2] + b0, acc[mt][nt][3] + b1);
            if (gc < K_E) {
                __half2 h0 = __floats2half2_rn(v0.x, v0.y);
                __half2 h1 = __floats2half2_rn(v1.x, v1.y);
                *(__half2*)&g_pvh[(size_t)r0 * PVLD + gc]       = h0;
                *(__half2*)&g_pvh[(size_t)(r0 + 8) * PVLD + gc] = h1;
            } else {
                *(float2*)&out_bbox[(size_t)r0 * K_C4 + (gc - K_E)]       = v0;
                *(float2*)&out_bbox[(size_t)(r0 + 8) * K_C4 + (gc - K_E)] = v1;
            }
        }
    }
}

// ---------------- scores GEMM: SCM=64 for 2 CTAs/SM ----------------
constexpr int SCM = 64, SCK = PVLD;                   // K = 320
constexpr int SC_LDB = SCK * 2;                       // 640 bytes per smem row
constexpr int SC_AB = SCM * SC_LDB;                   // 40960
constexpr int SC_BB = 96 * SC_LDB;                    // 61440
constexpr int SC_SMEM = SC_AB + SC_BB + 384;          // + sinv[64] + pad

__global__ __launch_bounds__(256, 2)
void scores_kernel(float* __restrict__ out_scores)
{
    extern __shared__ char smem[];
    const u32 sb = smem_u32(smem);
    float* sinv = (float*)(smem + SC_AB + SC_BB);
    const int tid  = threadIdx.x;
    const int wid  = tid >> 5;
    const int lane = tid & 31;
    const int wm   = wid & 3;            // 16-row band
    const int wn   = wid >> 2;           // 48-col band
    const int row0 = blockIdx.x * SCM;

    // one-shot loads: A 2560 chunks (10/thr), B 3840 chunks (15/thr)
    #pragma unroll
    for (int i = 0; i < 10; i++) {
        const int q = i * 256 + tid;
        const int row = q / 40, c16 = q % 40;
        CP_ASYNC16(sb + sw128((u32)(row * SC_LDB + c16 * 16)),
                   g_pvh + (size_t)(row0 + row) * SCK + c16 * 8);
    }
    #pragma unroll
    for (int i = 0; i < 15; i++) {
        const int q = i * 256 + tid;
        const int row = q / 40, c16 = q % 40;
        CP_ASYNC16(sb + SC_AB + sw128((u32)(row * SC_LDB + c16 * 16)),
                   g_neh + (size_t)row * SCK + c16 * 8);
    }
    CP_COMMIT();
    CP_WAIT0();
    __syncthreads();

    // row norms: warp wid handles rows wid*8..+7
    #pragma unroll
    for (int rr = 0; rr < 8; rr++) {
        const int row = wid * 8 + rr;
        float ss = 0.f;
        #pragma unroll
        for (int i = 0; i < 5; i++) {
            const int h = lane + 32 * i;              // half2 index 0..159
            u32 v;
            asm volatile("ld.shared.b32 %0, [%1];" : "=r"(v)
                         : "r"(sb + sw128((u32)(row * SC_LDB + h * 4))));
            float2 f = __half22float2(*reinterpret_cast<__half2*>(&v));
            ss = fmaf(f.x, f.x, fmaf(f.y, f.y, ss));
        }
        #pragma unroll
        for (int o = 16; o > 0; o >>= 1) ss += __shfl_xor_sync(0xffffffffu, ss, o);
        if (lane == 0) sinv[row] = 1.f / fmaxf(sqrtf(ss), 1e-12f);
    }
    __syncthreads();

    float acc[6][4];
    #pragma unroll
    for (int nt = 0; nt < 6; nt++)
        #pragma unroll
        for (int i = 0; i < 4; i++) acc[nt][i] = 0.f;

    const int lr15 = lane & 15;
    const int lhi  = lane >> 4;
    #pragma unroll 4
    for (int kt = 0; kt < SCK / 16; kt++) {           // 20 k-tiles
        u32 a[4];
        ldsm_x4(sb + sw128((u32)((wm * 16 + lr15) * SC_LDB + kt * 32 + lhi * 16)),
                a[0], a[1], a[2], a[3]);
        #pragma unroll
        for (int bt = 0; bt < 3; bt++) {
            u32 b[4];
            ldsm_x4(sb + SC_AB +
                    sw128((u32)((wn * 48 + bt * 16 + lr15) * SC_LDB + kt * 32 + lhi * 16)),
                    b[0], b[1], b[2], b[3]);
            mma_f16(acc[bt * 2 + 0], a, b[0], b[2]);
            mma_f16(acc[bt * 2 + 1], a, b[1], b[3]);
        }
    }

    // epilogue: scale and write cols < 81
    const int rl = wm * 16 + (lane >> 2);
    const float i0 = sinv[rl], i1 = sinv[rl + 8];
    const size_t o0 = (size_t)(row0 + rl) * K_C;
    const size_t o1 = (size_t)(row0 + rl + 8) * K_C;
    #pragma unroll
    for (int nt = 0; nt < 6; nt++) {
        const int c = wn * 48 + nt * 8 + (lane & 3) * 2;
        if (c < K_C) {
            out_scores[o0 + c] = acc[nt][0] * i0;
            out_scores[o1 + c] = acc[nt][2] * i1;
        }
        if (c + 1 < K_C) {
            out_scores[o0 + c + 1] = acc[nt][1] * i0;
            out_scores[o1 + c + 1] = acc[nt][3] * i1;
        }
    }
}

// ---------------- launch ----------------
extern "C" void kernel_launch(void* const* d_in, const int* in_sizes, int n_in,
                              void* d_out, int out_size)
{
    const float* x  = (const float*)d_in[0];
    const float* se = (const float*)d_in[1];
    const float* Wf = (const float*)d_in[2];
    const float* bf = (const float*)d_in[3];
    const float* We = (const float*)d_in[4];
    const float* be = (const float*)d_in[5];
    const float* Wb = (const float*)d_in[6];
    const float* bb = (const float*)d_in[7];

    float* out        = (float*)d_out;
    float* out_scores = out;
    float* out_bbox   = out + (size_t)K_N * K_C;
    float* out_loss   = out + (size_t)K_N * (K_C + K_C4);

    static bool attr_done = false;
    if (!attr_done) {
        cudaFuncSetAttribute(gemm_kernel, cudaFuncAttributeMaxDynamicSharedMemorySize, GEMM_SMEM);
        cudaFuncSetAttribute(scores_kernel, cudaFuncAttributeMaxDynamicSharedMemorySize, SC_SMEM);
        attr_done = true;
    }

    whalf_kernel<<<K_NPAD, 256>>>(Wf, Wb);                      // 0
    pe_kernel<<<96, 320>>>(se, We, be);                         // 1

    dim3 grid((K_NC + BN - 1) / BN, K_N / BM);                  // (5, 512)
    gemm_kernel<<<grid, 256, GEMM_SMEM>>>(x, bf, bb, out_bbox); // 2

    scores_kernel<<<K_N / SCM, 256, SC_SMEM>>>(out_scores);     // 3 (ncu capture slot)

    norm_sen_kernel<<<K_C, 128>>>(se);                          // 4
    sim_kernel<<<K_C, 256>>>();                                 // 5
    loss_kernel<<<1, 96>>>(out_loss);                           // 6
}

// round 10
// speedup vs baseline: 1.2392x; 1.2392x over previous
#include <cuda_runtime.h>
#include <cuda_fp16.h>
#include <cstdint>

typedef unsigned long long u64;
typedef unsigned int u32;

constexpr int K_N  = 65536;
constexpr int K_IC = 1024;
constexpr int K_E  = 300;
constexpr int K_C  = 81;
constexpr int K_C4 = 324;
constexpr int K_NC = K_E + K_C4;   // 624
constexpr int K_NPAD = 640;        // padded W rows
constexpr int K_KK = 1024;
constexpr int PVLD = 320;          // padded pv row length (halves)

// ---------------- scratch ----------------
__device__ __half g_xh[(size_t)K_N * K_KK];      // x as fp16
__device__ __half g_wh[(size_t)K_NPAD * K_KK];   // [Wf;Wb] fp16, rows>=624 zero
__device__ __half g_pvh[(size_t)K_N * PVLD];     // projected_visual fp16, cols>=300 zero
__device__ __half g_neh[96 * PVLD];              // l2norm(proj_emb) fp16, padded zero
__device__ float g_pe[K_C * K_E];                // projected_emb fp32 (triplet)
__device__ float g_sen[K_C * K_E];
__device__ float g_S[K_C * K_C];

// ---------------- helpers ----------------
__device__ __forceinline__ u32 smem_u32(const void* p) {
    u32 a;
    asm("{ .reg .u64 t; cvta.to.shared.u64 t, %1; cvt.u32.u64 %0, t; }" : "=r"(a) : "l"(p));
    return a;
}
__device__ __forceinline__ u32 sw128(u32 off) { return off ^ ((off >> 3) & 0x70); }

#define CP_ASYNC16(dst, src) \
    asm volatile("cp.async.cg.shared.global [%0], [%1], 16;" :: "r"(dst), "l"(src) : "memory")
#define CP_COMMIT() asm volatile("cp.async.commit_group;" ::: "memory")
#define CP_WAIT1()  asm volatile("cp.async.wait_group 1;" ::: "memory")
#define CP_WAIT0()  asm volatile("cp.async.wait_group 0;" ::: "memory")

__device__ __forceinline__ void ldsm_x4(u32 addr, u32& r0, u32& r1, u32& r2, u32& r3) {
    asm volatile("ldmatrix.sync.aligned.m8n8.x4.shared.b16 {%0,%1,%2,%3}, [%4];"
                 : "=r"(r0), "=r"(r1), "=r"(r2), "=r"(r3) : "r"(addr));
}
__device__ __forceinline__ void mma_f16(float* d, const u32* a, u32 b0, u32 b1) {
    asm volatile(
        "mma.sync.aligned.m16n8k16.row.col.f32.f16.f16.f32 "
        "{%0,%1,%2,%3}, {%4,%5,%6,%7}, {%8,%9}, {%0,%1,%2,%3};"
        : "+f"(d[0]), "+f"(d[1]), "+f"(d[2]), "+f"(d[3])
        : "r"(a[0]), "r"(a[1]), "r"(a[2]), "r"(a[3]), "r"(b0), "r"(b1));
}
__device__ __forceinline__ u32 h2u(__half2 h) { return *reinterpret_cast<u32*>(&h); }

// ---------------- prep: x and W -> fp16 (merged, R8-proven) ----------------
__global__ void xwhalf_kernel(const float* __restrict__ x,
                              const float* __restrict__ Wf,
                              const float* __restrict__ Wb)
{
    const int b = blockIdx.x;
    if (b < K_N) {
        const int id = b * 256 + threadIdx.x;
        float4 v = *(const float4*)(x + (size_t)id * 4);
        uint2 hu = make_uint2(h2u(__floats2half2_rn(v.x, v.y)),
                              h2u(__floats2half2_rn(v.z, v.w)));
        *(uint2*)(g_xh + (size_t)id * 4) = hu;
    } else {
        const int row = b - K_N;           // 0..639
        const int c4  = threadIdx.x;       // 0..255
        float4 v = make_float4(0.f, 0.f, 0.f, 0.f);
        if (row < K_E)        v = *(const float4*)(Wf + (size_t)row * K_IC + c4 * 4);
        else if (row < K_NC)  v = *(const float4*)(Wb + (size_t)(row - K_E) * K_IC + c4 * 4);
        uint2 hu = make_uint2(h2u(__floats2half2_rn(v.x, v.y)),
                              h2u(__floats2half2_rn(v.z, v.w)));
        *(uint2*)(g_wh + (size_t)row * K_KK + c4 * 4) = hu;
    }
}

// ---------------- pe: projected_emb + normalized fp16 table ----------------
__global__ void pe_kernel(const float* __restrict__ se,
                          const float* __restrict__ We,
                          const float* __restrict__ be)
{
    const int c = blockIdx.x;
    const int e = threadIdx.x;             // 0..319
    if (c >= K_C) {
        g_neh[c * PVLD + e] = __float2half(0.f);
        return;
    }
    __shared__ float srow[K_E];
    __shared__ float red[320];
    for (int k = e; k < K_E; k += 320) srow[k] = se[(size_t)c * K_E + k];
    __syncthreads();
    float v = 0.f;
    if (e < K_E) {
        const float* w = We + (size_t)e * K_E;
        float s = 0.f;
        for (int k = 0; k < K_E; k++) s = fmaf(srow[k], w[k], s);
        v = s + be[e];
        g_pe[(size_t)c * K_E + e] = v;
    }
    red[e] = v * v;
    __syncthreads();
    if (e == 0) {
        float s = 0.f;
        for (int i = 0; i < 320; i++) s += red[i];
        red[0] = 1.f / fmaxf(sqrtf(s), 1e-12f);
    }
    __syncthreads();
    g_neh[c * PVLD + e] = __float2half((e < K_E) ? v * red[0] : 0.f);
}

// ---------------- triplet stages ----------------
__global__ void norm_sen_kernel(const float* __restrict__ se)
{
    const int c = blockIdx.x;
    const int t = threadIdx.x;
    __shared__ float red[128];
    float s = 0.f;
    const float* row = se + (size_t)c * K_E;
    for (int k = t; k < K_E; k += 128) { float v = row[k]; s = fmaf(v, v, s); }
    red[t] = s;
    __syncthreads();
    #pragma unroll
    for (int off = 64; off > 0; off >>= 1) {
        if (t < off) red[t] += red[t + off];
        __syncthreads();
    }
    const float inv = 1.f / fmaxf(sqrtf(red[0]), 1e-12f);
    for (int k = t; k < K_E; k += 128) g_sen[(size_t)c * K_E + k] = row[k] * inv;
}

__global__ void sim_kernel()
{
    const int i = blockIdx.x;
    const int t = threadIdx.x;
    const int w = t >> 5, l = t & 31;
    __shared__ float rowi[K_E];
    for (int k = t; k < K_E; k += 256) rowi[k] = g_sen[(size_t)i * K_E + k];
    __syncthreads();
    for (int j = w; j < K_C; j += 8) {
        const float* b = g_sen + (size_t)j * K_E;
        float s = 0.f;
        for (int k = l; k < K_E; k += 32) s = fmaf(rowi[k], b[k], s);
        #pragma unroll
        for (int o = 16; o > 0; o >>= 1) s += __shfl_xor_sync(0xffffffffu, s, o);
        if (l == 0) g_S[i * K_C + j] = s;
    }
}

__global__ void loss_kernel(float* __restrict__ out_loss)
{
    const int t = threadIdx.x;             // 96
    __shared__ float red[96];
    float contrib = 0.f;
    if (t < K_C) {
        const float* Srow = g_S + (size_t)t * K_C;
        float mx = -1e30f;
        for (int j = 0; j < K_C; j++) {
            float v = Srow[j];
            if (v != 1.0f) mx = fmaxf(mx, v);
        }
        float sum = 0.f;
        for (int j = 0; j < K_C; j++) {
            float v = Srow[j];
            if (v != 1.0f) sum += expf(v - mx);
        }
        float m1 = -1e30f, m2 = -1e30f; int i1 = -1, i2 = -1;
        float mn = 1e30f; int imn = -1;
        for (int j = 0; j < K_C; j++) {
            float v = Srow[j];
            float sm = (v == 1.0f) ? v : (expf(v - mx) / sum);
            if (sm > m1)      { m2 = m1; i2 = i1; m1 = sm; i1 = j; }
            else if (sm > m2) { m2 = sm; i2 = j; }
            if (sm <= mn)     { mn = sm; imn = j; }
        }
        const int ms = i2, ls = imn;
        const float margin = m2 - mn;
        const float* pi = g_pe + (size_t)t  * K_E;
        const float* pm = g_pe + (size_t)ms * K_E;
        const float* pl = g_pe + (size_t)ls * K_E;
        float ds = 0.f, dd = 0.f;
        for (int k = 0; k < K_E; k++) {
            float d1 = pi[k] - pm[k]; ds = fmaf(d1, d1, ds);
            float d2 = pi[k] - pl[k]; dd = fmaf(d2, d2, dd);
        }
        contrib = fmaxf(0.f, sqrtf(ds) - sqrtf(dd) + margin);
    }
    red[t] = contrib;
    __syncthreads();
    if (t == 0) {
        float s = 0.f;
        for (int i = 0; i < 96; i++) s += red[i];
        out_loss[0] = s / (float)K_C;
    }
}

// ---------------- main GEMM (R8-proven): 3-stage cp.async, single-barrier mainloop ----------------
constexpr int BM = 128, BN = 128, BK = 64;
constexpr int NKT = K_KK / BK;         // 16
constexpr int STAGES = 3;
constexpr int AB = BM * BK * 2;        // 16384
constexpr int STGB = 2 * AB;           // 32768
constexpr int GEMM_SMEM = STAGES * STGB;

__device__ __forceinline__ void load_stage(u32 sdst, int tid, int row0, int nc0, int kt)
{
    const int koff = kt * BK;
    #pragma unroll
    for (int i = 0; i < 8; i++) {
        const int q = i * 256 + tid;
        if (q < 1024) {
            const int row = q >> 3, kb = q & 7;
            const __half* src = g_xh + (size_t)(row0 + row) * K_KK + koff + kb * 8;
            CP_ASYNC16(sdst + sw128((u32)(row * 128 + kb * 16)), src);
        } else {
            const int qq = q - 1024;
            const int row = qq >> 3, kb = qq & 7;
            const __half* src = g_wh + (size_t)(nc0 + row) * K_KK + koff + kb * 8;
            CP_ASYNC16(sdst + AB + sw128((u32)(row * 128 + kb * 16)), src);
        }
    }
}

__global__ __launch_bounds__(256, 2)
void gemm_kernel(const float* __restrict__ bfp, const float* __restrict__ bbp,
                 float* __restrict__ out_bbox)
{
    extern __shared__ char smem[];
    __shared__ float sbias[BN];
    const u32 sb = smem_u32(smem);

    const int tid  = threadIdx.x;
    const int wid  = tid >> 5;
    const int lane = tid & 31;
    const int wm   = wid & 3;
    const int wn   = wid >> 2;
    const int nc0  = blockIdx.x * BN;
    const int row0 = blockIdx.y * BM;

    if (tid < BN) {
        const int gc = nc0 + tid;
        sbias[tid] = (gc < K_E) ? bfp[gc] : ((gc < K_NC) ? bbp[gc - K_E] : 0.f);
    }

    float acc[2][8][4];
    #pragma unroll
    for (int mt = 0; mt < 2; mt++)
        #pragma unroll
        for (int nt = 0; nt < 8; nt++)
            #pragma unroll
            for (int i = 0; i < 4; i++) acc[mt][nt][i] = 0.f;

    load_stage(sb, tid, row0, nc0, 0);            CP_COMMIT();
    load_stage(sb + STGB, tid, row0, nc0, 1);     CP_COMMIT();

    const int lr15 = lane & 15;
    const int lkc  = lane >> 4;

    for (int kt = 0; kt < NKT; kt++) {
        CP_WAIT1();                // stage kt%3 ready
        __syncthreads();           // all warps past compute(kt-1): safe to overwrite (kt+2)%3

        const int lt = kt + 2;
        if (lt < NKT) load_stage(sb + (lt % STAGES) * STGB, tid, row0, nc0, lt);
        CP_COMMIT();               // unconditional: keeps group ledger aligned

        const u32 abase = sb + (kt % STAGES) * STGB;
        const u32 bbase = abase + AB;
        #pragma unroll
        for (int j = 0; j < 4; j++) {
            const int kc = j * 2 + lkc;
            u32 a[2][4], b[4][4];
            #pragma unroll
            for (int mt = 0; mt < 2; mt++) {
                const int r = wm * 32 + mt * 16 + lr15;
                ldsm_x4(abase + sw128((u32)(r * 128 + kc * 16)),
                        a[mt][0], a[mt][1], a[mt][2], a[mt][3]);
            }
            #pragma unroll
            for (int nt4 = 0; nt4 < 4; nt4++) {
                const int r = wn * 64 + nt4 * 16 + lr15;
                ldsm_x4(bbase + sw128((u32)(r * 128 + kc * 16)),
                        b[nt4][0], b[nt4][1], b[nt4][2], b[nt4][3]);
            }
            #pragma unroll
            for (int mt = 0; mt < 2; mt++)
                #pragma unroll
                for (int nt4 = 0; nt4 < 4; nt4++) {
                    mma_f16(acc[mt][nt4 * 2 + 0], a[mt], b[nt4][0], b[nt4][2]);
                    mma_f16(acc[mt][nt4 * 2 + 1], a[mt], b[nt4][1], b[nt4][3]);
                }
        }
    }

    // ---- epilogue: bias + scatter (pv fp16, bbox fp32) ----
    const int lr = lane >> 2;
    const int lc = (lane & 3) * 2;
    #pragma unroll
    for (int mt = 0; mt < 2; mt++) {
        const int r0 = row0 + wm * 32 + mt * 16 + lr;
        #pragma unroll
        for (int nt = 0; nt < 8; nt++) {
            const int lcol = wn * 64 + nt * 8 + lc;
            const int gc = nc0 + lcol;
            if (gc >= K_NC) continue;
            const float b0 = sbias[lcol], b1 = sbias[lcol + 1];
            float2 v0 = make_float2(acc[mt][nt][0] + b0, acc[mt][nt][1] + b1);
            float2 v1 = make_float2(acc[mt][nt][2] + b0, acc[mt][nt][3] + b1);
            if (gc < K_E) {
                __half2 h0 = __floats2half2_rn(v0.x, v0.y);
                __half2 h1 = __floats2half2_rn(v1.x, v1.y);
                *(__half2*)&g_pvh[(size_t)r0 * PVLD + gc]       = h0;
                *(__half2*)&g_pvh[(size_t)(r0 + 8) * PVLD + gc] = h1;
            } else {
                *(float2*)&out_bbox[(size_t)r0 * K_C4 + (gc - K_E)]       = v0;
                *(float2*)&out_bbox[(size_t)(r0 + 8) * K_C4 + (gc - K_E)] = v1;
            }
        }
    }
}

// ---------------- scores GEMM (R9-proven): SCM=64, 2 CTAs/SM ----------------
constexpr int SCM = 64, SCK = PVLD;                   // K = 320
constexpr int SC_LDB = SCK * 2;                       // 640 bytes per smem row
constexpr int SC_AB = SCM * SC_LDB;                   // 40960
constexpr int SC_BB = 96 * SC_LDB;                    // 61440
constexpr int SC_SMEM = SC_AB + SC_BB + 384;

__global__ __launch_bounds__(256, 2)
void scores_kernel(float* __restrict__ out_scores)
{
    extern __shared__ char smem[];
    const u32 sb = smem_u32(smem);
    float* sinv = (float*)(smem + SC_AB + SC_BB);
    const int tid  = threadIdx.x;
    const int wid  = tid >> 5;
    const int lane = tid & 31;
    const int wm   = wid & 3;            // 16-row band
    const int wn   = wid >> 2;           // 48-col band
    const int row0 = blockIdx.x * SCM;

    #pragma unroll
    for (int i = 0; i < 10; i++) {
        const int q = i * 256 + tid;
        const int row = q / 40, c16 = q % 40;
        CP_ASYNC16(sb + sw128((u32)(row * SC_LDB + c16 * 16)),
                   g_pvh + (size_t)(row0 + row) * SCK + c16 * 8);
    }
    #pragma unroll
    for (int i = 0; i < 15; i++) {
        const int q = i * 256 + tid;
        const int row = q / 40, c16 = q % 40;
        CP_ASYNC16(sb + SC_AB + sw128((u32)(row * SC_LDB + c16 * 16)),
                   g_neh + (size_t)row * SCK + c16 * 8);
    }
    CP_COMMIT();
    CP_WAIT0();
    __syncthreads();

    #pragma unroll
    for (int rr = 0; rr < 8; rr++) {
        const int row = wid * 8 + rr;
        float ss = 0.f;
        #pragma unroll
        for (int i = 0; i < 5; i++) {
            const int h = lane + 32 * i;
            u32 v;
            asm volatile("ld.shared.b32 %0, [%1];" : "=r"(v)
                         : "r"(sb + sw128((u32)(row * SC_LDB + h * 4))));
            float2 f = __half22float2(*reinterpret_cast<__half2*>(&v));
            ss = fmaf(f.x, f.x, fmaf(f.y, f.y, ss));
        }
        #pragma unroll
        for (int o = 16; o > 0; o >>= 1) ss += __shfl_xor_sync(0xffffffffu, ss, o);
        if (lane == 0) sinv[row] = 1.f / fmaxf(sqrtf(ss), 1e-12f);
    }
    __syncthreads();

    float acc[6][4];
    #pragma unroll
    for (int nt = 0; nt < 6; nt++)
        #pragma unroll
        for (int i = 0; i < 4; i++) acc[nt][i] = 0.f;

    const int lr15 = lane & 15;
    const int lhi  = lane >> 4;
    #pragma unroll 4
    for (int kt = 0; kt < SCK / 16; kt++) {           // 20 k-tiles
        u32 a[4];
        ldsm_x4(sb + sw128((u32)((wm * 16 + lr15) * SC_LDB + kt * 32 + lhi * 16)),
                a[0], a[1], a[2], a[3]);
        #pragma unroll
        for (int bt = 0; bt < 3; bt++) {
            u32 b[4];
            ldsm_x4(sb + SC_AB +
                    sw128((u32)((wn * 48 + bt * 16 + lr15) * SC_LDB + kt * 32 + lhi * 16)),
                    b[0], b[1], b[2], b[3]);
            mma_f16(acc[bt * 2 + 0], a, b[0], b[2]);
            mma_f16(acc[bt * 2 + 1], a, b[1], b[3]);
        }
    }

    const int rl = wm * 16 + (lane >> 2);
    const float i0 = sinv[rl], i1 = sinv[rl + 8];
    const size_t o0 = (size_t)(row0 + rl) * K_C;
    const size_t o1 = (size_t)(row0 + rl + 8) * K_C;
    #pragma unroll
    for (int nt = 0; nt < 6; nt++) {
        const int c = wn * 48 + nt * 8 + (lane & 3) * 2;
        if (c < K_C) {
            out_scores[o0 + c] = acc[nt][0] * i0;
            out_scores[o1 + c] = acc[nt][2] * i1;
        }
        if (c + 1 < K_C) {
            out_scores[o0 + c + 1] = acc[nt][1] * i0;
            out_scores[o1 + c + 1] = acc[nt][3] * i1;
        }
    }
}

// ---------------- launch ----------------
extern "C" void kernel_launch(void* const* d_in, const int* in_sizes, int n_in,
                              void* d_out, int out_size)
{
    const float* x  = (const float*)d_in[0];
    const float* se = (const float*)d_in[1];
    const float* Wf = (const float*)d_in[2];
    const float* bf = (const float*)d_in[3];
    const float* We = (const float*)d_in[4];
    const float* be = (const float*)d_in[5];
    const float* Wb = (const float*)d_in[6];
    const float* bb = (const float*)d_in[7];

    float* out        = (float*)d_out;
    float* out_scores = out;
    float* out_bbox   = out + (size_t)K_N * K_C;
    float* out_loss   = out + (size_t)K_N * (K_C + K_C4);

    static bool attr_done = false;
    if (!attr_done) {
        cudaFuncSetAttribute(gemm_kernel, cudaFuncAttributeMaxDynamicSharedMemorySize, GEMM_SMEM);
        cudaFuncSetAttribute(scores_kernel, cudaFuncAttributeMaxDynamicSharedMemorySize, SC_SMEM);
        attr_done = true;
    }

    xwhalf_kernel<<<K_N + K_NPAD, 256>>>(x, Wf, Wb);            // 0
    pe_kernel<<<96, 320>>>(se, We, be);                         // 1

    dim3 grid((K_NC + BN - 1) / BN, K_N / BM);                  // (5, 512)
    gemm_kernel<<<grid, 256, GEMM_SMEM>>>(bf, bb, out_bbox);    // 2

    scores_kernel<<<K_N / SCM, 256, SC_SMEM>>>(out_scores);     // 3 (ncu capture slot)

    norm_sen_kernel<<<K_C, 128>>>(se);                          // 4
    sim_kernel<<<K_C, 256>>>();                                 // 5
    loss_kernel<<<1, 96>>>(out_loss);                           // 6
}

// round 11
// speedup vs baseline: 1.3118x; 1.0586x over previous
#include <cuda_runtime.h>
#include <cuda_fp16.h>
#include <cstdint>

typedef unsigned long long u64;
typedef unsigned int u32;

constexpr int K_N  = 65536;
constexpr int K_IC = 1024;
constexpr int K_E  = 300;
constexpr int K_C  = 81;
constexpr int K_C4 = 324;
constexpr int K_NC = K_E + K_C4;   // 624
constexpr int K_NPAD = 640;        // padded W rows
constexpr int K_KK = 1024;
constexpr int PVLD = 320;          // padded pv row length (halves)

// ---------------- scratch ----------------
__device__ __half g_xh[(size_t)K_N * K_KK];      // x as fp16
__device__ __half g_wh[(size_t)K_NPAD * K_KK];   // [Wf;Wb] fp16, rows>=624 zero
__device__ __half g_pvh[(size_t)K_N * PVLD];     // projected_visual fp16, cols>=300 zero
__device__ __half g_neh[96 * PVLD];              // l2norm(proj_emb) fp16, padded zero
__device__ float g_pe[K_C * K_E];                // projected_emb fp32 (triplet)
__device__ float g_sen[K_C * K_E];
__device__ float g_S[K_C * K_C];

// ---------------- helpers ----------------
__device__ __forceinline__ u32 smem_u32(const void* p) {
    u32 a;
    asm("{ .reg .u64 t; cvta.to.shared.u64 t, %1; cvt.u32.u64 %0, t; }" : "=r"(a) : "l"(p));
    return a;
}
__device__ __forceinline__ u32 sw128(u32 off) { return off ^ ((off >> 3) & 0x70); }

#define CP_ASYNC16(dst, src) \
    asm volatile("cp.async.cg.shared.global [%0], [%1], 16;" :: "r"(dst), "l"(src) : "memory")
#define CP_COMMIT() asm volatile("cp.async.commit_group;" ::: "memory")
#define CP_WAIT1()  asm volatile("cp.async.wait_group 1;" ::: "memory")
#define CP_WAIT0()  asm volatile("cp.async.wait_group 0;" ::: "memory")

__device__ __forceinline__ void ldsm_x4(u32 addr, u32& r0, u32& r1, u32& r2, u32& r3) {
    asm volatile("ldmatrix.sync.aligned.m8n8.x4.shared.b16 {%0,%1,%2,%3}, [%4];"
                 : "=r"(r0), "=r"(r1), "=r"(r2), "=r"(r3) : "r"(addr));
}
__device__ __forceinline__ void mma_f16(float* d, const u32* a, u32 b0, u32 b1) {
    asm volatile(
        "mma.sync.aligned.m16n8k16.row.col.f32.f16.f16.f32 "
        "{%0,%1,%2,%3}, {%4,%5,%6,%7}, {%8,%9}, {%0,%1,%2,%3};"
        : "+f"(d[0]), "+f"(d[1]), "+f"(d[2]), "+f"(d[3])
        : "r"(a[0]), "r"(a[1]), "r"(a[2]), "r"(a[3]), "r"(b0), "r"(b1));
}
__device__ __forceinline__ u32 h2u(__half2 h) { return *reinterpret_cast<u32*>(&h); }

// ---------------- prep: x and W -> fp16 (merged) ----------------
__global__ void xwhalf_kernel(const float* __restrict__ x,
                              const float* __restrict__ Wf,
                              const float* __restrict__ Wb)
{
    const int b = blockIdx.x;
    if (b < K_N) {
        const int id = b * 256 + threadIdx.x;
        float4 v = *(const float4*)(x + (size_t)id * 4);
        uint2 hu = make_uint2(h2u(__floats2half2_rn(v.x, v.y)),
                              h2u(__floats2half2_rn(v.z, v.w)));
        *(uint2*)(g_xh + (size_t)id * 4) = hu;
    } else {
        const int row = b - K_N;           // 0..639
        const int c4  = threadIdx.x;       // 0..255
        float4 v = make_float4(0.f, 0.f, 0.f, 0.f);
        if (row < K_E)        v = *(const float4*)(Wf + (size_t)row * K_IC + c4 * 4);
        else if (row < K_NC)  v = *(const float4*)(Wb + (size_t)(row - K_E) * K_IC + c4 * 4);
        uint2 hu = make_uint2(h2u(__floats2half2_rn(v.x, v.y)),
                              h2u(__floats2half2_rn(v.z, v.w)));
        *(uint2*)(g_wh + (size_t)row * K_KK + c4 * 4) = hu;
    }
}

// ---------------- pe: projected_emb + normalized fp16 table ----------------
__global__ void pe_kernel(const float* __restrict__ se,
                          const float* __restrict__ We,
                          const float* __restrict__ be)
{
    const int c = blockIdx.x;
    const int e = threadIdx.x;             // 0..319
    if (c >= K_C) {
        g_neh[c * PVLD + e] = __float2half(0.f);
        return;
    }
    __shared__ float srow[K_E];
    __shared__ float red[320];
    for (int k = e; k < K_E; k += 320) srow[k] = se[(size_t)c * K_E + k];
    __syncthreads();
    float v = 0.f;
    if (e < K_E) {
        const float* w = We + (size_t)e * K_E;
        float s = 0.f;
        for (int k = 0; k < K_E; k++) s = fmaf(srow[k], w[k], s);
        v = s + be[e];
        g_pe[(size_t)c * K_E + e] = v;
    }
    red[e] = v * v;
    __syncthreads();
    if (e == 0) {
        float s = 0.f;
        for (int i = 0; i < 320; i++) s += red[i];
        red[0] = 1.f / fmaxf(sqrtf(s), 1e-12f);
    }
    __syncthreads();
    g_neh[c * PVLD + e] = __float2half((e < K_E) ? v * red[0] : 0.f);
}

// ---------------- triplet stages ----------------
__global__ void norm_sen_kernel(const float* __restrict__ se)
{
    const int c = blockIdx.x;
    const int t = threadIdx.x;
    __shared__ float red[128];
    float s = 0.f;
    const float* row = se + (size_t)c * K_E;
    for (int k = t; k < K_E; k += 128) { float v = row[k]; s = fmaf(v, v, s); }
    red[t] = s;
    __syncthreads();
    #pragma unroll
    for (int off = 64; off > 0; off >>= 1) {
        if (t < off) red[t] += red[t + off];
        __syncthreads();
    }
    const float inv = 1.f / fmaxf(sqrtf(red[0]), 1e-12f);
    for (int k = t; k < K_E; k += 128) g_sen[(size_t)c * K_E + k] = row[k] * inv;
}

__global__ void sim_kernel()
{
    const int i = blockIdx.x;
    const int t = threadIdx.x;
    const int w = t >> 5, l = t & 31;
    __shared__ float rowi[K_E];
    for (int k = t; k < K_E; k += 256) rowi[k] = g_sen[(size_t)i * K_E + k];
    __syncthreads();
    for (int j = w; j < K_C; j += 8) {
        const float* b = g_sen + (size_t)j * K_E;
        float s = 0.f;
        for (int k = l; k < K_E; k += 32) s = fmaf(rowi[k], b[k], s);
        #pragma unroll
        for (int o = 16; o > 0; o >>= 1) s += __shfl_xor_sync(0xffffffffu, s, o);
        if (l == 0) g_S[i * K_C + j] = s;
    }
}

__global__ void loss_kernel(float* __restrict__ out_loss)
{
    const int t = threadIdx.x;             // 96
    __shared__ float red[96];
    float contrib = 0.f;
    if (t < K_C) {
        const float* Srow = g_S + (size_t)t * K_C;
        float mx = -1e30f;
        for (int j = 0; j < K_C; j++) {
            float v = Srow[j];
            if (v != 1.0f) mx = fmaxf(mx, v);
        }
        float sum = 0.f;
        for (int j = 0; j < K_C; j++) {
            float v = Srow[j];
            if (v != 1.0f) sum += expf(v - mx);
        }
        float m1 = -1e30f, m2 = -1e30f; int i1 = -1, i2 = -1;
        float mn = 1e30f; int imn = -1;
        for (int j = 0; j < K_C; j++) {
            float v = Srow[j];
            float sm = (v == 1.0f) ? v : (expf(v - mx) / sum);
            if (sm > m1)      { m2 = m1; i2 = i1; m1 = sm; i1 = j; }
            else if (sm > m2) { m2 = sm; i2 = j; }
            if (sm <= mn)     { mn = sm; imn = j; }
        }
        const int ms = i2, ls = imn;
        const float margin = m2 - mn;
        const float* pi = g_pe + (size_t)t  * K_E;
        const float* pm = g_pe + (size_t)ms * K_E;
        const float* pl = g_pe + (size_t)ls * K_E;
        float ds = 0.f, dd = 0.f;
        for (int k = 0; k < K_E; k++) {
            float d1 = pi[k] - pm[k]; ds = fmaf(d1, d1, ds);
            float d2 = pi[k] - pl[k]; dd = fmaf(d2, d2, dd);
        }
        contrib = fmaxf(0.f, sqrtf(ds) - sqrtf(dd) + margin);
    }
    red[t] = contrib;
    __syncthreads();
    if (t == 0) {
        float s = 0.f;
        for (int i = 0; i < 96; i++) s += red[i];
        out_loss[0] = s / (float)K_C;
    }
}

// ---------------- main GEMM: 3-stage cp.async, single-barrier mainloop ----------------
constexpr int BM = 128, BN = 128, BK = 64;
constexpr int NKT = K_KK / BK;         // 16
constexpr int STAGES = 3;
constexpr int AB = BM * BK * 2;        // 16384
constexpr int STGB = 2 * AB;           // 32768
constexpr int GEMM_SMEM = STAGES * STGB;

__device__ __forceinline__ void load_stage(u32 sdst, int tid, int row0, int nc0, int kt)
{
    const int koff = kt * BK;
    #pragma unroll
    for (int i = 0; i < 8; i++) {
        const int q = i * 256 + tid;
        if (q < 1024) {
            const int row = q >> 3, kb = q & 7;
            const __half* src = g_xh + (size_t)(row0 + row) * K_KK + koff + kb * 8;
            CP_ASYNC16(sdst + sw128((u32)(row * 128 + kb * 16)), src);
        } else {
            const int qq = q - 1024;
            const int row = qq >> 3, kb = qq & 7;
            const __half* src = g_wh + (size_t)(nc0 + row) * K_KK + koff + kb * 8;
            CP_ASYNC16(sdst + AB + sw128((u32)(row * 128 + kb * 16)), src);
        }
    }
}

__global__ __launch_bounds__(256, 2)
void gemm_kernel(const float* __restrict__ bfp, const float* __restrict__ bbp,
                 float* __restrict__ out_bbox)
{
    extern __shared__ char smem[];
    __shared__ float sbias[BN];
    const u32 sb = smem_u32(smem);

    const int tid  = threadIdx.x;
    const int wid  = tid >> 5;
    const int lane = tid & 31;
    const int wm   = wid & 3;
    const int wn   = wid >> 2;
    const int nc0  = blockIdx.x * BN;
    const int row0 = blockIdx.y * BM;

    if (tid < BN) {
        const int gc = nc0 + tid;
        sbias[tid] = (gc < K_E) ? bfp[gc] : ((gc < K_NC) ? bbp[gc - K_E] : 0.f);
    }

    float acc[2][8][4];
    #pragma unroll
    for (int mt = 0; mt < 2; mt++)
        #pragma unroll
        for (int nt = 0; nt < 8; nt++)
            #pragma unroll
            for (int i = 0; i < 4; i++) acc[mt][nt][i] = 0.f;

    load_stage(sb, tid, row0, nc0, 0);            CP_COMMIT();
    load_stage(sb + STGB, tid, row0, nc0, 1);     CP_COMMIT();

    const int lr15 = lane & 15;
    const int lkc  = lane >> 4;

    for (int kt = 0; kt < NKT; kt++) {
        CP_WAIT1();                // stage kt%3 ready
        __syncthreads();           // all warps past compute(kt-1): safe to overwrite (kt+2)%3

        const int lt = kt + 2;
        if (lt < NKT) load_stage(sb + (lt % STAGES) * STGB, tid, row0, nc0, lt);
        CP_COMMIT();               // unconditional: keeps group ledger aligned

        const u32 abase = sb + (kt % STAGES) * STGB;
        const u32 bbase = abase + AB;
        #pragma unroll
        for (int j = 0; j < 4; j++) {
            const int kc = j * 2 + lkc;
            u32 a[2][4], b[4][4];
            #pragma unroll
            for (int mt = 0; mt < 2; mt++) {
                const int r = wm * 32 + mt * 16 + lr15;
                ldsm_x4(abase + sw128((u32)(r * 128 + kc * 16)),
                        a[mt][0], a[mt][1], a[mt][2], a[mt][3]);
            }
            #pragma unroll
            for (int nt4 = 0; nt4 < 4; nt4++) {
                const int r = wn * 64 + nt4 * 16 + lr15;
                ldsm_x4(bbase + sw128((u32)(r * 128 + kc * 16)),
                        b[nt4][0], b[nt4][1], b[nt4][2], b[nt4][3]);
            }
            #pragma unroll
            for (int mt = 0; mt < 2; mt++)
                #pragma unroll
                for (int nt4 = 0; nt4 < 4; nt4++) {
                    mma_f16(acc[mt][nt4 * 2 + 0], a[mt], b[nt4][0], b[nt4][2]);
                    mma_f16(acc[mt][nt4 * 2 + 1], a[mt], b[nt4][1], b[nt4][3]);
                }
        }
    }

    // ---- epilogue: bias + scatter (pv fp16, bbox fp32) ----
    const int lr = lane >> 2;
    const int lc = (lane & 3) * 2;
    #pragma unroll
    for (int mt = 0; mt < 2; mt++) {
        const int r0 = row0 + wm * 32 + mt * 16 + lr;
        #pragma unroll
        for (int nt = 0; nt < 8; nt++) {
            const int lcol = wn * 64 + nt * 8 + lc;
            const int gc = nc0 + lcol;
            if (gc >= K_NC) continue;
            const float b0 = sbias[lcol], b1 = sbias[lcol + 1];
            float2 v0 = make_float2(acc[mt][nt][0] + b0, acc[mt][nt][1] + b1);
            float2 v1 = make_float2(acc[mt][nt][2] + b0, acc[mt][nt][3] + b1);
            if (gc < K_E) {
                __half2 h0 = __floats2half2_rn(v0.x, v0.y);
                __half2 h1 = __floats2half2_rn(v1.x, v1.y);
                *(__half2*)&g_pvh[(size_t)r0 * PVLD + gc]       = h0;
                *(__half2*)&g_pvh[(size_t)(r0 + 8) * PVLD + gc] = h1;
            } else {
                *(float2*)&out_bbox[(size_t)r0 * K_C4 + (gc - K_E)]       = v0;
                *(float2*)&out_bbox[(size_t)(r0 + 8) * K_C4 + (gc - K_E)] = v1;
            }
        }
    }
}

// ---------------- scores GEMM: SCM=64, 2 CTAs/SM ----------------
constexpr int SCM = 64, SCK = PVLD;                   // K = 320
constexpr int SC_LDB = SCK * 2;                       // 640 bytes per smem row
constexpr int SC_AB = SCM * SC_LDB;                   // 40960
constexpr int SC_BB = 96 * SC_LDB;                    // 61440
constexpr int SC_SMEM = SC_AB + SC_BB + 384;

__global__ __launch_bounds__(256, 2)
void scores_kernel(float* __restrict__ out_scores)
{
    extern __shared__ char smem[];
    const u32 sb = smem_u32(smem);
    float* sinv = (float*)(smem + SC_AB + SC_BB);
    const int tid  = threadIdx.x;
    const int wid  = tid >> 5;
    const int lane = tid & 31;
    const int wm   = wid & 3;            // 16-row band
    const int wn   = wid >> 2;           // 48-col band
    const int row0 = blockIdx.x * SCM;

    #pragma unroll
    for (int i = 0; i < 10; i++) {
        const int q = i * 256 + tid;
        const int row = q / 40, c16 = q % 40;
        CP_ASYNC16(sb + sw128((u32)(row * SC_LDB + c16 * 16)),
                   g_pvh + (size_t)(row0 + row) * SCK + c16 * 8);
    }
    #pragma unroll
    for (int i = 0; i < 15; i++) {
        const int q = i * 256 + tid;
        const int row = q / 40, c16 = q % 40;
        CP_ASYNC16(sb + SC_AB + sw128((u32)(row * SC_LDB + c16 * 16)),
                   g_neh + (size_t)row * SCK + c16 * 8);
    }
    CP_COMMIT();
    CP_WAIT0();
    __syncthreads();

    #pragma unroll
    for (int rr = 0; rr < 8; rr++) {
        const int row = wid * 8 + rr;
        float ss = 0.f;
        #pragma unroll
        for (int i = 0; i < 5; i++) {
            const int h = lane + 32 * i;
            u32 v;
            asm volatile("ld.shared.b32 %0, [%1];" : "=r"(v)
                         : "r"(sb + sw128((u32)(row * SC_LDB + h * 4))));
            float2 f = __half22float2(*reinterpret_cast<__half2*>(&v));
            ss = fmaf(f.x, f.x, fmaf(f.y, f.y, ss));
        }
        #pragma unroll
        for (int o = 16; o > 0; o >>= 1) ss += __shfl_xor_sync(0xffffffffu, ss, o);
        if (lane == 0) sinv[row] = 1.f / fmaxf(sqrtf(ss), 1e-12f);
    }
    __syncthreads();

    float acc[6][4];
    #pragma unroll
    for (int nt = 0; nt < 6; nt++)
        #pragma unroll
        for (int i = 0; i < 4; i++) acc[nt][i] = 0.f;

    const int lr15 = lane & 15;
    const int lhi  = lane >> 4;
    #pragma unroll 4
    for (int kt = 0; kt < SCK / 16; kt++) {           // 20 k-tiles
        u32 a[4];
        ldsm_x4(sb + sw128((u32)((wm * 16 + lr15) * SC_LDB + kt * 32 + lhi * 16)),
                a[0], a[1], a[2], a[3]);
        #pragma unroll
        for (int bt = 0; bt < 3; bt++) {
            u32 b[4];
            ldsm_x4(sb + SC_AB +
                    sw128((u32)((wn * 48 + bt * 16 + lr15) * SC_LDB + kt * 32 + lhi * 16)),
                    b[0], b[1], b[2], b[3]);
            mma_f16(acc[bt * 2 + 0], a, b[0], b[2]);
            mma_f16(acc[bt * 2 + 1], a, b[1], b[3]);
        }
    }

    const int rl = wm * 16 + (lane >> 2);
    const float i0 = sinv[rl], i1 = sinv[rl + 8];
    const size_t o0 = (size_t)(row0 + rl) * K_C;
    const size_t o1 = (size_t)(row0 + rl + 8) * K_C;
    #pragma unroll
    for (int nt = 0; nt < 6; nt++) {
        const int c = wn * 48 + nt * 8 + (lane & 3) * 2;
        if (c < K_C) {
            out_scores[o0 + c] = acc[nt][0] * i0;
            out_scores[o1 + c] = acc[nt][2] * i1;
        }
        if (c + 1 < K_C) {
            out_scores[o0 + c + 1] = acc[nt][1] * i0;
            out_scores[o1 + c + 1] = acc[nt][3] * i1;
        }
    }
}

// ---------------- launch: fork/join two independent chains ----------------
extern "C" void kernel_launch(void* const* d_in, const int* in_sizes, int n_in,
                              void* d_out, int out_size)
{
    const float* x  = (const float*)d_in[0];
    const float* se = (const float*)d_in[1];
    const float* Wf = (const float*)d_in[2];
    const float* bf = (const float*)d_in[3];
    const float* We = (const float*)d_in[4];
    const float* be = (const float*)d_in[5];
    const float* Wb = (const float*)d_in[6];
    const float* bb = (const float*)d_in[7];

    float* out        = (float*)d_out;
    float* out_scores = out;
    float* out_bbox   = out + (size_t)K_N * K_C;
    float* out_loss   = out + (size_t)K_N * (K_C + K_C4);

    static cudaStream_t s2 = nullptr;
    static cudaEvent_t evFork = nullptr, evJoin = nullptr;
    static bool init_done = false;
    if (!init_done) {
        cudaFuncSetAttribute(gemm_kernel, cudaFuncAttributeMaxDynamicSharedMemorySize, GEMM_SMEM);
        cudaFuncSetAttribute(scores_kernel, cudaFuncAttributeMaxDynamicSharedMemorySize, SC_SMEM);
        cudaStreamCreateWithFlags(&s2, cudaStreamNonBlocking);
        cudaEventCreateWithFlags(&evFork, cudaEventDisableTiming);
        cudaEventCreateWithFlags(&evJoin, cudaEventDisableTiming);
        init_done = true;
    }

    // fork: side chain (pe + triplet) runs concurrently with xwhalf+gemm
    cudaEventRecord(evFork, 0);
    cudaStreamWaitEvent(s2, evFork, 0);

    pe_kernel<<<96, 320, 0, s2>>>(se, We, be);
    norm_sen_kernel<<<K_C, 128, 0, s2>>>(se);
    sim_kernel<<<K_C, 256, 0, s2>>>();
    loss_kernel<<<1, 96, 0, s2>>>(out_loss);
    cudaEventRecord(evJoin, s2);

    // main chain
    xwhalf_kernel<<<K_N + K_NPAD, 256>>>(x, Wf, Wb);

    dim3 grid((K_NC + BN - 1) / BN, K_N / BM);   // (5, 512)
    gemm_kernel<<<grid, 256, GEMM_SMEM>>>(bf, bb, out_bbox);

    // join: scores needs g_neh (pe); side chain is long done by now
    cudaStreamWaitEvent(0, evJoin, 0);
    scores_kernel<<<K_N / SCM, 256, SC_SMEM>>>(out_scores);
}

// round 12
// speedup vs baseline: 1.4493x; 1.1049x over previous
#include <cuda_runtime.h>
#include <cuda_fp16.h>
#include <cstdint>

typedef unsigned long long u64;
typedef unsigned int u32;

constexpr int K_N  = 65536;
constexpr int K_IC = 1024;
constexpr int K_E  = 300;
constexpr int K_C  = 81;
constexpr int K_C4 = 324;
constexpr int K_NC = K_E + K_C4;   // 624
constexpr int K_NPAD = 640;        // padded W rows
constexpr int K_KK = 1024;
constexpr int PVLD = 320;          // padded pv row length (halves)
constexpr int HALF_N = K_N / 2;    // 32768-row chunks

// ---------------- scratch ----------------
__device__ __half g_xh[(size_t)K_N * K_KK];      // x as fp16
__device__ __half g_wh[(size_t)K_NPAD * K_KK];   // [Wf;Wb] fp16, rows>=624 zero
__device__ __half g_pvh[(size_t)K_N * PVLD];     // projected_visual fp16, cols>=300 zero
__device__ __half g_neh[96 * PVLD];              // l2norm(proj_emb) fp16, padded zero
__device__ float g_pe[K_C * K_E];                // projected_emb fp32 (triplet)
__device__ float g_sen[K_C * K_E];
__device__ float g_S[K_C * K_C];

// ---------------- helpers ----------------
__device__ __forceinline__ u32 smem_u32(const void* p) {
    u32 a;
    asm("{ .reg .u64 t; cvta.to.shared.u64 t, %1; cvt.u32.u64 %0, t; }" : "=r"(a) : "l"(p));
    return a;
}
__device__ __forceinline__ u32 sw128(u32 off) { return off ^ ((off >> 3) & 0x70); }

#define CP_ASYNC16(dst, src) \
    asm volatile("cp.async.cg.shared.global [%0], [%1], 16;" :: "r"(dst), "l"(src) : "memory")
#define CP_COMMIT() asm volatile("cp.async.commit_group;" ::: "memory")
#define CP_WAIT1()  asm volatile("cp.async.wait_group 1;" ::: "memory")
#define CP_WAIT0()  asm volatile("cp.async.wait_group 0;" ::: "memory")

__device__ __forceinline__ void ldsm_x4(u32 addr, u32& r0, u32& r1, u32& r2, u32& r3) {
    asm volatile("ldmatrix.sync.aligned.m8n8.x4.shared.b16 {%0,%1,%2,%3}, [%4];"
                 : "=r"(r0), "=r"(r1), "=r"(r2), "=r"(r3) : "r"(addr));
}
__device__ __forceinline__ void mma_f16(float* d, const u32* a, u32 b0, u32 b1) {
    asm volatile(
        "mma.sync.aligned.m16n8k16.row.col.f32.f16.f16.f32 "
        "{%0,%1,%2,%3}, {%4,%5,%6,%7}, {%8,%9}, {%0,%1,%2,%3};"
        : "+f"(d[0]), "+f"(d[1]), "+f"(d[2]), "+f"(d[3])
        : "r"(a[0]), "r"(a[1]), "r"(a[2]), "r"(a[3]), "r"(b0), "r"(b1));
}
__device__ __forceinline__ u32 h2u(__half2 h) { return *reinterpret_cast<u32*>(&h); }

// ---------------- prep: x rows [base, base+nx) -> fp16; optionally W ----------------
__global__ void xwhalf_kernel(const float* __restrict__ x,
                              const float* __restrict__ Wf,
                              const float* __restrict__ Wb,
                              int x_row_base, int n_x_rows)
{
    const int b = blockIdx.x;
    if (b < n_x_rows) {
        const size_t id = ((size_t)(x_row_base + b)) * 256 + threadIdx.x;
        float4 v = *(const float4*)(x + id * 4);
        uint2 hu = make_uint2(h2u(__floats2half2_rn(v.x, v.y)),
                              h2u(__floats2half2_rn(v.z, v.w)));
        *(uint2*)(g_xh + id * 4) = hu;
    } else {
        const int row = b - n_x_rows;      // 0..639 (grid sized only when W needed)
        const int c4  = threadIdx.x;       // 0..255
        float4 v = make_float4(0.f, 0.f, 0.f, 0.f);
        if (row < K_E)        v = *(const float4*)(Wf + (size_t)row * K_IC + c4 * 4);
        else if (row < K_NC)  v = *(const float4*)(Wb + (size_t)(row - K_E) * K_IC + c4 * 4);
        uint2 hu = make_uint2(h2u(__floats2half2_rn(v.x, v.y)),
                              h2u(__floats2half2_rn(v.z, v.w)));
        *(uint2*)(g_wh + (size_t)row * K_KK + c4 * 4) = hu;
    }
}

// ---------------- pe: projected_emb + normalized fp16 table ----------------
__global__ void pe_kernel(const float* __restrict__ se,
                          const float* __restrict__ We,
                          const float* __restrict__ be)
{
    const int c = blockIdx.x;
    const int e = threadIdx.x;             // 0..319
    if (c >= K_C) {
        g_neh[c * PVLD + e] = __float2half(0.f);
        return;
    }
    __shared__ float srow[K_E];
    __shared__ float red[320];
    for (int k = e; k < K_E; k += 320) srow[k] = se[(size_t)c * K_E + k];
    __syncthreads();
    float v = 0.f;
    if (e < K_E) {
        const float* w = We + (size_t)e * K_E;
        float s = 0.f;
        for (int k = 0; k < K_E; k++) s = fmaf(srow[k], w[k], s);
        v = s + be[e];
        g_pe[(size_t)c * K_E + e] = v;
    }
    red[e] = v * v;
    __syncthreads();
    if (e == 0) {
        float s = 0.f;
        for (int i = 0; i < 320; i++) s += red[i];
        red[0] = 1.f / fmaxf(sqrtf(s), 1e-12f);
    }
    __syncthreads();
    g_neh[c * PVLD + e] = __float2half((e < K_E) ? v * red[0] : 0.f);
}

// ---------------- triplet stages ----------------
__global__ void norm_sen_kernel(const float* __restrict__ se)
{
    const int c = blockIdx.x;
    const int t = threadIdx.x;
    __shared__ float red[128];
    float s = 0.f;
    const float* row = se + (size_t)c * K_E;
    for (int k = t; k < K_E; k += 128) { float v = row[k]; s = fmaf(v, v, s); }
    red[t] = s;
    __syncthreads();
    #pragma unroll
    for (int off = 64; off > 0; off >>= 1) {
        if (t < off) red[t] += red[t + off];
        __syncthreads();
    }
    const float inv = 1.f / fmaxf(sqrtf(red[0]), 1e-12f);
    for (int k = t; k < K_E; k += 128) g_sen[(size_t)c * K_E + k] = row[k] * inv;
}

__global__ void sim_kernel()
{
    const int i = blockIdx.x;
    const int t = threadIdx.x;
    const int w = t >> 5, l = t & 31;
    __shared__ float rowi[K_E];
    for (int k = t; k < K_E; k += 256) rowi[k] = g_sen[(size_t)i * K_E + k];
    __syncthreads();
    for (int j = w; j < K_C; j += 8) {
        const float* b = g_sen + (size_t)j * K_E;
        float s = 0.f;
        for (int k = l; k < K_E; k += 32) s = fmaf(rowi[k], b[k], s);
        #pragma unroll
        for (int o = 16; o > 0; o >>= 1) s += __shfl_xor_sync(0xffffffffu, s, o);
        if (l == 0) g_S[i * K_C + j] = s;
    }
}

__global__ void loss_kernel(float* __restrict__ out_loss)
{
    const int t = threadIdx.x;             // 96
    __shared__ float red[96];
    float contrib = 0.f;
    if (t < K_C) {
        const float* Srow = g_S + (size_t)t * K_C;
        float mx = -1e30f;
        for (int j = 0; j < K_C; j++) {
            float v = Srow[j];
            if (v != 1.0f) mx = fmaxf(mx, v);
        }
        float sum = 0.f;
        for (int j = 0; j < K_C; j++) {
            float v = Srow[j];
            if (v != 1.0f) sum += expf(v - mx);
        }
        float m1 = -1e30f, m2 = -1e30f; int i1 = -1, i2 = -1;
        float mn = 1e30f; int imn = -1;
        for (int j = 0; j < K_C; j++) {
            float v = Srow[j];
            float sm = (v == 1.0f) ? v : (expf(v - mx) / sum);
            if (sm > m1)      { m2 = m1; i2 = i1; m1 = sm; i1 = j; }
            else if (sm > m2) { m2 = sm; i2 = j; }
            if (sm <= mn)     { mn = sm; imn = j; }
        }
        const int ms = i2, ls = imn;
        const float margin = m2 - mn;
        const float* pi = g_pe + (size_t)t  * K_E;
        const float* pm = g_pe + (size_t)ms * K_E;
        const float* pl = g_pe + (size_t)ls * K_E;
        float ds = 0.f, dd = 0.f;
        for (int k = 0; k < K_E; k++) {
            float d1 = pi[k] - pm[k]; ds = fmaf(d1, d1, ds);
            float d2 = pi[k] - pl[k]; dd = fmaf(d2, d2, dd);
        }
        contrib = fmaxf(0.f, sqrtf(ds) - sqrtf(dd) + margin);
    }
    red[t] = contrib;
    __syncthreads();
    if (t == 0) {
        float s = 0.f;
        for (int i = 0; i < 96; i++) s += red[i];
        out_loss[0] = s / (float)K_C;
    }
}

// ---------------- main GEMM: 3-stage cp.async, single-barrier mainloop ----------------
constexpr int BM = 128, BN = 128, BK = 64;
constexpr int NKT = K_KK / BK;         // 16
constexpr int STAGES = 3;
constexpr int AB = BM * BK * 2;        // 16384
constexpr int STGB = 2 * AB;           // 32768
constexpr int GEMM_SMEM = STAGES * STGB;

__device__ __forceinline__ void load_stage(u32 sdst, int tid, int row0, int nc0, int kt)
{
    const int koff = kt * BK;
    #pragma unroll
    for (int i = 0; i < 8; i++) {
        const int q = i * 256 + tid;
        if (q < 1024) {
            const int row = q >> 3, kb = q & 7;
            const __half* src = g_xh + (size_t)(row0 + row) * K_KK + koff + kb * 8;
            CP_ASYNC16(sdst + sw128((u32)(row * 128 + kb * 16)), src);
        } else {
            const int qq = q - 1024;
            const int row = qq >> 3, kb = qq & 7;
            const __half* src = g_wh + (size_t)(nc0 + row) * K_KK + koff + kb * 8;
            CP_ASYNC16(sdst + AB + sw128((u32)(row * 128 + kb * 16)), src);
        }
    }
}

__global__ __launch_bounds__(256, 2)
void gemm_kernel(const float* __restrict__ bfp, const float* __restrict__ bbp,
                 float* __restrict__ out_bbox, int row_base)
{
    extern __shared__ char smem[];
    __shared__ float sbias[BN];
    const u32 sb = smem_u32(smem);

    const int tid  = threadIdx.x;
    const int wid  = tid >> 5;
    const int lane = tid & 31;
    const int wm   = wid & 3;
    const int wn   = wid >> 2;
    const int nc0  = blockIdx.x * BN;
    const int row0 = row_base + blockIdx.y * BM;

    if (tid < BN) {
        const int gc = nc0 + tid;
        sbias[tid] = (gc < K_E) ? bfp[gc] : ((gc < K_NC) ? bbp[gc - K_E] : 0.f);
    }

    float acc[2][8][4];
    #pragma unroll
    for (int mt = 0; mt < 2; mt++)
        #pragma unroll
        for (int nt = 0; nt < 8; nt++)
            #pragma unroll
            for (int i = 0; i < 4; i++) acc[mt][nt][i] = 0.f;

    load_stage(sb, tid, row0, nc0, 0);            CP_COMMIT();
    load_stage(sb + STGB, tid, row0, nc0, 1);     CP_COMMIT();

    const int lr15 = lane & 15;
    const int lkc  = lane >> 4;

    for (int kt = 0; kt < NKT; kt++) {
        CP_WAIT1();                // stage kt%3 ready
        __syncthreads();           // all warps past compute(kt-1): safe to overwrite (kt+2)%3

        const int lt = kt + 2;
        if (lt < NKT) load_stage(sb + (lt % STAGES) * STGB, tid, row0, nc0, lt);
        CP_COMMIT();               // unconditional: keeps group ledger aligned

        const u32 abase = sb + (kt % STAGES) * STGB;
        const u32 bbase = abase + AB;
        #pragma unroll
        for (int j = 0; j < 4; j++) {
            const int kc = j * 2 + lkc;
            u32 a[2][4], b[4][4];
            #pragma unroll
            for (int mt = 0; mt < 2; mt++) {
                const int r = wm * 32 + mt * 16 + lr15;
                ldsm_x4(abase + sw128((u32)(r * 128 + kc * 16)),
                        a[mt][0], a[mt][1], a[mt][2], a[mt][3]);
            }
            #pragma unroll
            for (int nt4 = 0; nt4 < 4; nt4++) {
                const int r = wn * 64 + nt4 * 16 + lr15;
                ldsm_x4(bbase + sw128((u32)(r * 128 + kc * 16)),
                        b[nt4][0], b[nt4][1], b[nt4][2], b[nt4][3]);
            }
            #pragma unroll
            for (int mt = 0; mt < 2; mt++)
                #pragma unroll
                for (int nt4 = 0; nt4 < 4; nt4++) {
                    mma_f16(acc[mt][nt4 * 2 + 0], a[mt], b[nt4][0], b[nt4][2]);
                    mma_f16(acc[mt][nt4 * 2 + 1], a[mt], b[nt4][1], b[nt4][3]);
                }
        }
    }

    // ---- epilogue: bias + scatter (pv fp16, bbox fp32) ----
    const int lr = lane >> 2;
    const int lc = (lane & 3) * 2;
    #pragma unroll
    for (int mt = 0; mt < 2; mt++) {
        const int r0 = row0 + wm * 32 + mt * 16 + lr;
        #pragma unroll
        for (int nt = 0; nt < 8; nt++) {
            const int lcol = wn * 64 + nt * 8 + lc;
            const int gc = nc0 + lcol;
            if (gc >= K_NC) continue;
            const float b0 = sbias[lcol], b1 = sbias[lcol + 1];
            float2 v0 = make_float2(acc[mt][nt][0] + b0, acc[mt][nt][1] + b1);
            float2 v1 = make_float2(acc[mt][nt][2] + b0, acc[mt][nt][3] + b1);
            if (gc < K_E) {
                __half2 h0 = __floats2half2_rn(v0.x, v0.y);
                __half2 h1 = __floats2half2_rn(v1.x, v1.y);
                *(__half2*)&g_pvh[(size_t)r0 * PVLD + gc]       = h0;
                *(__half2*)&g_pvh[(size_t)(r0 + 8) * PVLD + gc] = h1;
            } else {
                *(float2*)&out_bbox[(size_t)r0 * K_C4 + (gc - K_E)]       = v0;
                *(float2*)&out_bbox[(size_t)(r0 + 8) * K_C4 + (gc - K_E)] = v1;
            }
        }
    }
}

// ---------------- scores GEMM: SCM=64, 2 CTAs/SM ----------------
constexpr int SCM = 64, SCK = PVLD;                   // K = 320
constexpr int SC_LDB = SCK * 2;                       // 640 bytes per smem row
constexpr int SC_AB = SCM * SC_LDB;                   // 40960
constexpr int SC_BB = 96 * SC_LDB;                    // 61440
constexpr int SC_SMEM = SC_AB + SC_BB + 384;

__global__ __launch_bounds__(256, 2)
void scores_kernel(float* __restrict__ out_scores, int row_base)
{
    extern __shared__ char smem[];
    const u32 sb = smem_u32(smem);
    float* sinv = (float*)(smem + SC_AB + SC_BB);
    const int tid  = threadIdx.x;
    const int wid  = tid >> 5;
    const int lane = tid & 31;
    const int wm   = wid & 3;            // 16-row band
    const int wn   = wid >> 2;           // 48-col band
    const int row0 = row_base + blockIdx.x * SCM;

    #pragma unroll
    for (int i = 0; i < 10; i++) {
        const int q = i * 256 + tid;
        const int row = q / 40, c16 = q % 40;
        CP_ASYNC16(sb + sw128((u32)(row * SC_LDB + c16 * 16)),
                   g_pvh + (size_t)(row0 + row) * SCK + c16 * 8);
    }
    #pragma unroll
    for (int i = 0; i < 15; i++) {
        const int q = i * 256 + tid;
        const int row = q / 40, c16 = q % 40;
        CP_ASYNC16(sb + SC_AB + sw128((u32)(row * SC_LDB + c16 * 16)),
                   g_neh + (size_t)row * SCK + c16 * 8);
    }
    CP_COMMIT();
    CP_WAIT0();
    __syncthreads();

    #pragma unroll
    for (int rr = 0; rr < 8; rr++) {
        const int row = wid * 8 + rr;
        float ss = 0.f;
        #pragma unroll
        for (int i = 0; i < 5; i++) {
            const int h = lane + 32 * i;
            u32 v;
            asm volatile("ld.shared.b32 %0, [%1];" : "=r"(v)
                         : "r"(sb + sw128((u32)(row * SC_LDB + h * 4))));
            float2 f = __half22float2(*reinterpret_cast<__half2*>(&v));
            ss = fmaf(f.x, f.x, fmaf(f.y, f.y, ss));
        }
        #pragma unroll
        for (int o = 16; o > 0; o >>= 1) ss += __shfl_xor_sync(0xffffffffu, ss, o);
        if (lane == 0) sinv[row] = 1.f / fmaxf(sqrtf(ss), 1e-12f);
    }
    __syncthreads();

    float acc[6][4];
    #pragma unroll
    for (int nt = 0; nt < 6; nt++)
        #pragma unroll
        for (int i = 0; i < 4; i++) acc[nt][i] = 0.f;

    const int lr15 = lane & 15;
    const int lhi  = lane >> 4;
    #pragma unroll 4
    for (int kt = 0; kt < SCK / 16; kt++) {           // 20 k-tiles
        u32 a[4];
        ldsm_x4(sb + sw128((u32)((wm * 16 + lr15) * SC_LDB + kt * 32 + lhi * 16)),
                a[0], a[1], a[2], a[3]);
        #pragma unroll
        for (int bt = 0; bt < 3; bt++) {
            u32 b[4];
            ldsm_x4(sb + SC_AB +
                    sw128((u32)((wn * 48 + bt * 16 + lr15) * SC_LDB + kt * 32 + lhi * 16)),
                    b[0], b[1], b[2], b[3]);
            mma_f16(acc[bt * 2 + 0], a, b[0], b[2]);
            mma_f16(acc[bt * 2 + 1], a, b[1], b[3]);
        }
    }

    const int rl = wm * 16 + (lane >> 2);
    const float i0 = sinv[rl], i1 = sinv[rl + 8];
    const size_t o0 = (size_t)(row0 + rl) * K_C;
    const size_t o1 = (size_t)(row0 + rl + 8) * K_C;
    #pragma unroll
    for (int nt = 0; nt < 6; nt++) {
        const int c = wn * 48 + nt * 8 + (lane & 3) * 2;
        if (c < K_C) {
            out_scores[o0 + c] = acc[nt][0] * i0;
            out_scores[o1 + c] = acc[nt][2] * i1;
        }
        if (c + 1 < K_C) {
            out_scores[o0 + c + 1] = acc[nt][1] * i0;
            out_scores[o1 + c + 1] = acc[nt][3] * i1;
        }
    }
}

// ---------------- launch: 3-stream chunked pipeline ----------------
extern "C" void kernel_launch(void* const* d_in, const int* in_sizes, int n_in,
                              void* d_out, int out_size)
{
    const float* x  = (const float*)d_in[0];
    const float* se = (const float*)d_in[1];
    const float* Wf = (const float*)d_in[2];
    const float* bf = (const float*)d_in[3];
    const float* We = (const float*)d_in[4];
    const float* be = (const float*)d_in[5];
    const float* Wb = (const float*)d_in[6];
    const float* bb = (const float*)d_in[7];

    float* out        = (float*)d_out;
    float* out_scores = out;
    float* out_bbox   = out + (size_t)K_N * K_C;
    float* out_loss   = out + (size_t)K_N * (K_C + K_C4);

    static cudaStream_t sX = nullptr, s2 = nullptr, sS = nullptr;
    static cudaEvent_t eFork, exw0, exw1, ePe, eg0, eg1, eSc, eLoss;
    static bool init_done = false;
    if (!init_done) {
        cudaFuncSetAttribute(gemm_kernel, cudaFuncAttributeMaxDynamicSharedMemorySize, GEMM_SMEM);
        cudaFuncSetAttribute(scores_kernel, cudaFuncAttributeMaxDynamicSharedMemorySize, SC_SMEM);
        cudaStreamCreateWithFlags(&sX, cudaStreamNonBlocking);
        cudaStreamCreateWithFlags(&s2, cudaStreamNonBlocking);
        cudaStreamCreateWithFlags(&sS, cudaStreamNonBlocking);
        cudaEventCreateWithFlags(&eFork, cudaEventDisableTiming);
        cudaEventCreateWithFlags(&exw0,  cudaEventDisableTiming);
        cudaEventCreateWithFlags(&exw1,  cudaEventDisableTiming);
        cudaEventCreateWithFlags(&ePe,   cudaEventDisableTiming);
        cudaEventCreateWithFlags(&eg0,   cudaEventDisableTiming);
        cudaEventCreateWithFlags(&eg1,   cudaEventDisableTiming);
        cudaEventCreateWithFlags(&eSc,   cudaEventDisableTiming);
        cudaEventCreateWithFlags(&eLoss, cudaEventDisableTiming);
        init_done = true;
    }

    // fork from origin stream
    cudaEventRecord(eFork, 0);
    cudaStreamWaitEvent(sX, eFork, 0);
    cudaStreamWaitEvent(s2, eFork, 0);
    cudaStreamWaitEvent(sS, eFork, 0);

    // sX: conversion chunks (chunk0 includes W)
    xwhalf_kernel<<<HALF_N + K_NPAD, 256, 0, sX>>>(x, Wf, Wb, 0, HALF_N);       // 0
    cudaEventRecord(exw0, sX);
    xwhalf_kernel<<<HALF_N, 256, 0, sX>>>(x, Wf, Wb, HALF_N, HALF_N);           // 1
    cudaEventRecord(exw1, sX);

    // s2: pe first (scores depends only on this), then triplet tail
    pe_kernel<<<96, 320, 0, s2>>>(se, We, be);                                  // 2
    cudaEventRecord(ePe, s2);

    // main: gemm chunk 0 (capture slot 3 — profiled)
    dim3 grid(5, HALF_N / BM);   // (5, 256)
    cudaStreamWaitEvent(0, exw0, 0);
    gemm_kernel<<<grid, 256, GEMM_SMEM>>>(bf, bb, out_bbox, 0);                 // 3
    cudaEventRecord(eg0, 0);

    norm_sen_kernel<<<K_C, 128, 0, s2>>>(se);                                   // 4
    sim_kernel<<<K_C, 256, 0, s2>>>();                                          // 5
    loss_kernel<<<1, 96, 0, s2>>>(out_loss);                                    // 6
    cudaEventRecord(eLoss, s2);

    // main: gemm chunk 1
    cudaStreamWaitEvent(0, exw1, 0);
    gemm_kernel<<<grid, 256, GEMM_SMEM>>>(bf, bb, out_bbox, HALF_N);            // 7
    cudaEventRecord(eg1, 0);

    // sS: scores chunks (chunk0 overlaps gemm chunk 1)
    cudaStreamWaitEvent(sS, ePe, 0);
    cudaStreamWaitEvent(sS, eg0, 0);
    scores_kernel<<<HALF_N / SCM, 256, SC_SMEM, sS>>>(out_scores, 0);           // 8
    cudaStreamWaitEvent(sS, eg1, 0);
    scores_kernel<<<HALF_N / SCM, 256, SC_SMEM, sS>>>(out_scores, HALF_N);      // 9
    cudaEventRecord(eSc, sS);

    // join everything back to origin stream
    cudaStreamWaitEvent(0, eSc, 0);
    cudaStreamWaitEvent(0, eLoss, 0);
}